// round 6
// baseline (speedup 1.0000x reference)
#include <cuda_runtime.h>

// ConceptGaussians: per-domain gather.
//   labels  : [B=2097152, C=8] int32, values in [0, 64)
//   mean    : [8, 64] float32
//   log_var : [8, 64] float32
// Output (tuple concatenated): [ means[B,8] | log_vars[B,8] ] float32,
// out_size = 2*B*8.
//
// DRAM-bound: 64 MiB label read + 128 MiB output write ≈ 201 MB total.
// Roofline @ ~6.5-7 TB/s effective: ~30 us.

__global__ void __launch_bounds__(256)
concept_gather_kernel(const int4* __restrict__ lab4,
                      const float* __restrict__ g_mean,
                      const float* __restrict__ g_lv,
                      float4* __restrict__ out_m,
                      float4* __restrict__ out_v,
                      int n)
{
    // Fused (mean, log_var) table: 8 domains x 64 concepts = 512 float2 = 4 KiB.
    __shared__ float2 tab[512];
    #pragma unroll
    for (int i = threadIdx.x; i < 512; i += 256)
        tab[i] = make_float2(g_mean[i], g_lv[i]);
    __syncthreads();

    int b = blockIdx.x * 256 + threadIdx.x;
    if (b >= n) return;

    // 8 labels for this sample: two vec4 loads (coalesced LDG.128).
    int4 l0 = lab4[2 * b];
    int4 l1 = lab4[2 * b + 1];

    // Per-domain lookups; domain d lives at tab[d*64 + idx].
    float2 t0 = tab[        l0.x];
    float2 t1 = tab[ 64  +  l0.y];
    float2 t2 = tab[128  +  l0.z];
    float2 t3 = tab[192  +  l0.w];
    float2 t4 = tab[256  +  l1.x];
    float2 t5 = tab[320  +  l1.y];
    float2 t6 = tab[384  +  l1.z];
    float2 t7 = tab[448  +  l1.w];

    // Coalesced STG.128 into the two output halves.
    out_m[2 * b]     = make_float4(t0.x, t1.x, t2.x, t3.x);
    out_m[2 * b + 1] = make_float4(t4.x, t5.x, t6.x, t7.x);
    out_v[2 * b]     = make_float4(t0.y, t1.y, t2.y, t3.y);
    out_v[2 * b + 1] = make_float4(t4.y, t5.y, t6.y, t7.y);
}

extern "C" void kernel_launch(void* const* d_in, const int* in_sizes, int n_in,
                              void* d_out, int out_size)
{
    const int4*  labels = (const int4*)d_in[0];           // [B,8] int32 as int4 pairs
    const float* g_mean = (const float*)d_in[1];          // [8,64]
    const float* g_lv   = (const float*)d_in[2];          // [8,64]

    int n = in_sizes[0] / 8;                              // B samples

    float4* out_m = (float4*)d_out;                       // means half: n*8 floats = n*2 float4
    float4* out_v = out_m + (size_t)n * 2;                // log_var half

    int blocks = (n + 255) / 256;
    concept_gather_kernel<<<blocks, 256>>>(labels, g_mean, g_lv, out_m, out_v, n);
}